// round 1
// baseline (speedup 1.0000x reference)
#include <cuda_runtime.h>
#include <cuda_bf16.h>
#include <cstdint>

// Problem: out = adabin_1bit(x) conv3x3(pad1) bwn(weight)
//   x: (32,256,56,56) f32, weight: (256,256,3,3) f32, out: (32,256,56,56) f32
// Exact factorization:
//   out[n,o,h,w] = alpha[n]*m[o]*(256*nvalid - 2*sum_taps popc(xbits^wbits))
// where bit = (val < 0), alpha[n] = max(2*mean|x_n|, 1e-5), m[o] = mean|w_o|.

#define N_ 32
#define C_ 256
#define H_ 56
#define W_ 56
#define O_ 256
#define HW_ (H_*W_)
#define CHW_ (C_*H_*W_)
#define NW_ 8            // 256 channels / 32 bits
#define NPART_ (H_*NW_)  // partials per sample = 448

// Scratch (device globals; no allocation allowed)
__device__ __align__(16) unsigned g_xpack[N_*H_*W_*NW_];   // [n][h][w][j]  3.2 MB
__device__ __align__(16) unsigned g_wpack[O_*9*NW_];       // [o][t][j]     73.7 KB
__device__ float g_partial[N_*NPART_];
__device__ float g_alpha[N_];
__device__ float g_m[O_];

// ---------------------------------------------------------------------------
// Kernel 1: pack x sign bits + per-(n,h,j) |x| partial sums (deterministic)
// grid (8 j, 56 h, 32 n), block 64 (w lanes, 56 active)
__global__ void pack_x_kernel(const float* __restrict__ x) {
    int j = blockIdx.x, h = blockIdx.y, n = blockIdx.z;
    int w = threadIdx.x;
    float s = 0.f;
    unsigned word = 0u;
    if (w < W_) {
        const float* base = x + ((size_t)n*C_ + (size_t)j*32)*HW_ + (size_t)h*W_ + w;
        #pragma unroll
        for (int i = 0; i < 32; ++i) {
            float v = base[(size_t)i*HW_];
            s += fabsf(v);
            word |= (unsigned)(v < 0.f) << i;
        }
        g_xpack[(((size_t)n*H_ + h)*W_ + w)*NW_ + j] = word;
    }
    __shared__ float red[64];
    red[threadIdx.x] = s;
    __syncthreads();
    #pragma unroll
    for (int off = 32; off > 0; off >>= 1) {
        if (threadIdx.x < off) red[threadIdx.x] += red[threadIdx.x + off];
        __syncthreads();
    }
    if (threadIdx.x == 0) g_partial[n*NPART_ + h*NW_ + j] = red[0];
}

// ---------------------------------------------------------------------------
// Kernel 2: alpha[n] = max(2*mean|x_n|, 1e-5). One block per sample.
__global__ void alpha_kernel() {
    int n = blockIdx.x;
    float s = 0.f;
    for (int t = threadIdx.x; t < NPART_; t += 64) s += g_partial[n*NPART_ + t];
    __shared__ float red[64];
    red[threadIdx.x] = s;
    __syncthreads();
    #pragma unroll
    for (int off = 32; off > 0; off >>= 1) {
        if (threadIdx.x < off) red[threadIdx.x] += red[threadIdx.x + off];
        __syncthreads();
    }
    if (threadIdx.x == 0)
        g_alpha[n] = fmaxf(2.f * red[0] * (1.f / (float)CHW_), 1e-5f);
}

// ---------------------------------------------------------------------------
// Kernel 3: pack weight sign bits + m[o]. One block per output channel.
__global__ void pack_w_kernel(const float* __restrict__ wt) {
    int o = blockIdx.x;
    const float* wo = wt + (size_t)o * (C_*9);
    float s = 0.f;
    for (int i = threadIdx.x; i < C_*9; i += 128) s += fabsf(wo[i]);
    if (threadIdx.x < 72) {
        int t = threadIdx.x / NW_;   // tap kh*3+kw
        int j = threadIdx.x % NW_;   // channel word
        unsigned word = 0u;
        #pragma unroll
        for (int i = 0; i < 32; ++i) {
            float v = wo[(j*32 + i)*9 + t];
            word |= (unsigned)(v < 0.f) << i;
        }
        g_wpack[((size_t)o*9 + t)*NW_ + j] = word;
    }
    __shared__ float red[128];
    red[threadIdx.x] = s;
    __syncthreads();
    #pragma unroll
    for (int off = 64; off > 0; off >>= 1) {
        if (threadIdx.x < off) red[threadIdx.x] += red[threadIdx.x + off];
        __syncthreads();
    }
    if (threadIdx.x == 0) g_m[o] = red[0] * (1.f / (float)(C_*9));
}

// ---------------------------------------------------------------------------
// Kernel 4: XNOR-popcount conv. Block = (n,h): 64x4 threads.
// Thread (w, oy) computes outputs for its w and o = oy*64 .. oy*64+63.
__global__ __launch_bounds__(256, 2)
void conv_kernel(float* __restrict__ out) {
    int h = blockIdx.x, n = blockIdx.y;
    __shared__ unsigned xs[3][64][NW_];   // rows h-1..h+1, col = w+1, zero border
    __shared__ float sm_m[O_];
    __shared__ float s_alpha;

    int tid = threadIdx.y * 64 + threadIdx.x;
    for (int idx = tid; idx < 3*64*NW_; idx += 256) ((unsigned*)xs)[idx] = 0u;
    if (tid < O_) sm_m[tid] = g_m[tid];
    if (tid == 0) s_alpha = g_alpha[n];
    __syncthreads();
    for (int idx = tid; idx < 3*W_*NW_; idx += 256) {
        int r = idx / (W_*NW_);
        int rem = idx % (W_*NW_);
        int w = rem / NW_, j = rem % NW_;
        int hr = h - 1 + r;
        if (hr >= 0 && hr < H_)
            xs[r][w + 1][j] = g_xpack[(((size_t)n*H_ + hr)*W_ + w)*NW_ + j];
    }
    __syncthreads();

    int w = threadIdx.x;
    if (w >= W_) return;
    int oy = threadIdx.y;

    // hoist this thread's x neighborhood into registers (reused across 256 o)
    unsigned xr[3][3][NW_];
    #pragma unroll
    for (int r = 0; r < 3; ++r)
        #pragma unroll
        for (int c = 0; c < 3; ++c)
            #pragma unroll
            for (int j = 0; j < NW_; ++j)
                xr[r][c][j] = xs[r][w + c][j];

    bool rv0 = (h > 0), rv2 = (h < H_-1);
    bool cv0 = (w > 0), cv2 = (w < W_-1);
    int nv = (1 + (int)rv0 + (int)rv2) * (1 + (int)cv0 + (int)cv2);
    int base = C_ * nv;
    float av = s_alpha;

    size_t outbase = ((size_t)n*O_)*HW_ + (size_t)h*W_ + w;
    int o0 = oy * 64;
    const uint4* wp = (const uint4*)&g_wpack[(size_t)o0 * 72];  // 18 uint4 per o

    for (int o = o0; o < o0 + 64; ++o, wp += 18) {
        int pc = 0;
        #pragma unroll
        for (int r = 0; r < 3; ++r) {
            if (r == 0 && !rv0) continue;       // uniform across block (h fixed)
            if (r == 2 && !rv2) continue;
            #pragma unroll
            for (int c = 0; c < 3; ++c) {
                bool cval = !((c == 0 && !cv0) || (c == 2 && !cv2));
                if (cval) {
                    int t = r*3 + c;
                    uint4 a = wp[t*2];
                    uint4 b = wp[t*2 + 1];
                    pc += __popc(xr[r][c][0] ^ a.x) + __popc(xr[r][c][1] ^ a.y)
                        + __popc(xr[r][c][2] ^ a.z) + __popc(xr[r][c][3] ^ a.w)
                        + __popc(xr[r][c][4] ^ b.x) + __popc(xr[r][c][5] ^ b.y)
                        + __popc(xr[r][c][6] ^ b.z) + __popc(xr[r][c][7] ^ b.w);
                }
            }
        }
        int dot = base - 2 * pc;
        out[outbase + (size_t)o * HW_] = av * sm_m[o] * (float)dot;
    }
}

// ---------------------------------------------------------------------------
extern "C" void kernel_launch(void* const* d_in, const int* in_sizes, int n_in,
                              void* d_out, int out_size) {
    const float* x  = (const float*)d_in[0];
    const float* wt = (const float*)d_in[1];
    float* out = (float*)d_out;

    pack_x_kernel<<<dim3(NW_, H_, N_), 64>>>(x);
    alpha_kernel<<<N_, 64>>>();
    pack_w_kernel<<<O_, 128>>>(wt);
    conv_kernel<<<dim3(H_, N_), dim3(64, 4)>>>(out);
}